// round 8
// baseline (speedup 1.0000x reference)
#include <cuda_runtime.h>
#include <cstdint>

#define BB    8192
#define NN    40
#define FF    256
#define NBLK  4
#define BLKSZ 10
#define NF    (NN * FF)          // 10240
#define EPSF  1e-5f
#define NSPLIT 64                // batch splits for stats reduction

// Scratch (static __device__ allocations, allowed by harness rules)
__device__ float g_S[(size_t)BB * NN * FF];          // 335 MB: S = X @ W
__device__ float g_psum[NSPLIT * NF];                // 2.6 MB: partial sums of Y
__device__ float g_psumsq[NSPLIT * NF];              // 2.6 MB: partial sum-squares
__device__ float g_scale[NF];
__device__ float g_shift[NF];

__device__ __forceinline__ uint32_t f2tf32(float f) {
    uint32_t r;
    asm("cvt.rna.tf32.f32 %0, %1;" : "=r"(r) : "f"(f));
    return r;
}

// ---------------------------------------------------------------------------
// K1: S = X @ W   [327680 x 256] @ [256 x 256], reading input directly.
// tf32 tensor-core GEMM via mma.sync.m16n8k8 (fp32 accumulate).
// CTA tile 128x128, K-step 32, 256 threads = 8 warps in 4(M) x 2(N).
// Warp tile 32x64 = 2(M-atoms of 16) x 8(N-atoms of 8).
// ---------------------------------------------------------------------------
#define AS_STRIDE 36    // (36g mod 32 = 4g) + t covers all 32 banks -> conflict-free
#define BS_STRIDE 136   // (136t mod 32 = 8t) + g covers all 32 banks -> conflict-free

__global__ void __launch_bounds__(256) k_gemm(const float* __restrict__ X,
                                              const float* __restrict__ Bw) {
    __shared__ uint32_t As[128 * AS_STRIDE];   // [m][k], tf32 bits
    __shared__ uint32_t Bs[32 * BS_STRIDE];    // [k][n], tf32 bits

    const int tid  = threadIdx.x;
    const int lane = tid & 31;
    const int wid  = tid >> 5;
    const int wm   = wid & 3;        // 0..3  -> M offset wm*32
    const int wn   = wid >> 2;       // 0..1  -> N offset wn*64
    const int g    = lane >> 2;      // groupID
    const int t    = lane & 3;       // threadID_in_group

    const size_t m0 = (size_t)blockIdx.x * 128;
    const int    n0 = blockIdx.y * 128;

    // global->smem load mappings (K-step 32)
    const int am = tid >> 1;               // 0..127 (A row)
    const int ak = (tid & 1) * 16;         // 0 or 16 (A k-chunk of 16)
    const int bk = tid >> 3;               // 0..31  (B k row)
    const int bn = (tid & 7) * 16;         // 0..112 (B n-chunk of 16)

    float c[2][8][4];
#pragma unroll
    for (int i = 0; i < 2; i++)
#pragma unroll
        for (int j = 0; j < 8; j++)
#pragma unroll
            for (int q = 0; q < 4; q++) c[i][j][q] = 0.f;

    for (int kk = 0; kk < 256; kk += 32) {
        // ---- load A tile [128 x 32] ----
        {
            const float* src = X + (m0 + am) * 256 + kk + ak;
            uint32_t* d = &As[am * AS_STRIDE + ak];
#pragma unroll
            for (int q = 0; q < 4; q++) {
                float4 v = *(const float4*)(src + q * 4);
                d[q * 4 + 0] = f2tf32(v.x); d[q * 4 + 1] = f2tf32(v.y);
                d[q * 4 + 2] = f2tf32(v.z); d[q * 4 + 3] = f2tf32(v.w);
            }
        }
        // ---- load B tile [32 x 128] ----
        {
            const float* src = Bw + (size_t)(kk + bk) * 256 + n0 + bn;
            uint32_t* d = &Bs[bk * BS_STRIDE + bn];
#pragma unroll
            for (int q = 0; q < 4; q++) {
                float4 v = *(const float4*)(src + q * 4);
                d[q * 4 + 0] = f2tf32(v.x); d[q * 4 + 1] = f2tf32(v.y);
                d[q * 4 + 2] = f2tf32(v.z); d[q * 4 + 3] = f2tf32(v.w);
            }
        }
        __syncthreads();

#pragma unroll
        for (int k0 = 0; k0 < 32; k0 += 8) {
            uint32_t a[2][4];
#pragma unroll
            for (int im = 0; im < 2; im++) {
                int rb = wm * 32 + im * 16;
                a[im][0] = As[(rb + g)     * AS_STRIDE + k0 + t];
                a[im][1] = As[(rb + g + 8) * AS_STRIDE + k0 + t];
                a[im][2] = As[(rb + g)     * AS_STRIDE + k0 + t + 4];
                a[im][3] = As[(rb + g + 8) * AS_STRIDE + k0 + t + 4];
            }
            uint32_t b[8][2];
#pragma unroll
            for (int in = 0; in < 8; in++) {
                int cb = wn * 64 + in * 8;
                b[in][0] = Bs[(k0 + t)     * BS_STRIDE + cb + g];
                b[in][1] = Bs[(k0 + t + 4) * BS_STRIDE + cb + g];
            }
#pragma unroll
            for (int im = 0; im < 2; im++)
#pragma unroll
                for (int in = 0; in < 8; in++) {
                    asm volatile(
                        "mma.sync.aligned.m16n8k8.row.col.f32.tf32.tf32.f32 "
                        "{%0,%1,%2,%3}, {%4,%5,%6,%7}, {%8,%9}, {%0,%1,%2,%3};"
                        : "+f"(c[im][in][0]), "+f"(c[im][in][1]),
                          "+f"(c[im][in][2]), "+f"(c[im][in][3])
                        : "r"(a[im][0]), "r"(a[im][1]), "r"(a[im][2]), "r"(a[im][3]),
                          "r"(b[in][0]), "r"(b[in][1]));
                }
        }
        __syncthreads();
    }

    // ---- epilogue: write S ----
#pragma unroll
    for (int im = 0; im < 2; im++) {
        size_t r0 = m0 + wm * 32 + im * 16 + g;
#pragma unroll
        for (int in = 0; in < 8; in++) {
            int col = n0 + wn * 64 + in * 8 + 2 * t;
            *(float2*)(g_S + r0 * 256 + col)       = make_float2(c[im][in][0], c[im][in][1]);
            *(float2*)(g_S + (r0 + 8) * 256 + col) = make_float2(c[im][in][2], c[im][in][3]);
        }
    }
}

// ---------------------------------------------------------------------------
// K2: stats with on-the-fly block-mix. Y[b,s+n,f] = sum_j adj[b,s+n,s+j]*S[b,s+j,f]
// grid (NBLK, NSPLIT), 256 threads (one per f). Deterministic, no atomics.
// Each CTA: one diag block, 128 batches; accumulates sum/sumsq for its 10 rows.
// ---------------------------------------------------------------------------
__global__ void __launch_bounds__(256) k_stats(const float* __restrict__ adj) {
    __shared__ float a_s[BLKSZ][BLKSZ];
    const int blk = blockIdx.x;
    const int sp  = blockIdx.y;
    const int s   = blk * BLKSZ;
    const int f   = threadIdx.x;
    const int b0  = sp * (BB / NSPLIT);

    float sum[BLKSZ], sq[BLKSZ];
#pragma unroll
    for (int n = 0; n < BLKSZ; n++) { sum[n] = 0.f; sq[n] = 0.f; }

    for (int b = b0; b < b0 + BB / NSPLIT; b++) {
        if (f < BLKSZ * BLKSZ) {
            int n = f / BLKSZ, j = f % BLKSZ;
            a_s[n][j] = adj[((size_t)b * NN + s + n) * NN + s + j];
        }
        __syncthreads();

        float x[BLKSZ];
#pragma unroll
        for (int j = 0; j < BLKSZ; j++)
            x[j] = g_S[((size_t)b * NN + s + j) * FF + f];

#pragma unroll
        for (int n = 0; n < BLKSZ; n++) {
            float y = 0.f;
#pragma unroll
            for (int j = 0; j < BLKSZ; j++)
                y = fmaf(a_s[n][j], x[j], y);
            sum[n] += y;
            sq[n]   = fmaf(y, y, sq[n]);
        }
        __syncthreads();
    }

#pragma unroll
    for (int n = 0; n < BLKSZ; n++) {
        g_psum[sp * NF + (s + n) * FF + f]   = sum[n];
        g_psumsq[sp * NF + (s + n) * FF + f] = sq[n];
    }
}

// ---------------------------------------------------------------------------
// K3: reduce partials, compute per-feature scale/shift.
// out = (Y - mean) * rsqrt(var+eps) * gamma[blk(n)]  +  sum_i beta[i]
// (rows outside block i contribute exactly beta[i] from that block's BN)
// ---------------------------------------------------------------------------
__global__ void k_finalize(const float* __restrict__ gamma,
                           const float* __restrict__ beta) {
    int i = blockIdx.x * blockDim.x + threadIdx.x;
    if (i >= NF) return;
    float s = 0.f, s2 = 0.f;
#pragma unroll 8
    for (int sp = 0; sp < NSPLIT; sp++) {
        s  += g_psum[sp * NF + i];
        s2 += g_psumsq[sp * NF + i];
    }
    const float inv = 1.f / (float)BB;
    float mean = s * inv;
    float var  = s2 * inv - mean * mean;
    int n   = i / FF;
    int blk = n / BLKSZ;
    float sc = rsqrtf(var + EPSF) * gamma[blk * NF + i];
    float sh = -mean * sc;
#pragma unroll
    for (int t = 0; t < NBLK; t++) sh += beta[t * NF + i];
    g_scale[i] = sc;
    g_shift[i] = sh;
}

// ---------------------------------------------------------------------------
// K4: recompute Y = mix(S), apply scale/shift, write out.
// grid (BB, NBLK), 256 threads (one per f)
// ---------------------------------------------------------------------------
__global__ void __launch_bounds__(256) k_norm(const float* __restrict__ adj,
                                              float* __restrict__ out) {
    __shared__ float a_s[BLKSZ][BLKSZ];
    const int b   = blockIdx.x;
    const int blk = blockIdx.y;
    const int s   = blk * BLKSZ;
    const int f   = threadIdx.x;

    if (f < BLKSZ * BLKSZ) {
        int n = f / BLKSZ, j = f % BLKSZ;
        a_s[n][j] = adj[((size_t)b * NN + s + n) * NN + s + j];
    }
    __syncthreads();

    float x[BLKSZ];
#pragma unroll
    for (int j = 0; j < BLKSZ; j++)
        x[j] = g_S[((size_t)b * NN + s + j) * FF + f];

#pragma unroll
    for (int n = 0; n < BLKSZ; n++) {
        float y = 0.f;
#pragma unroll
        for (int j = 0; j < BLKSZ; j++)
            y = fmaf(a_s[n][j], x[j], y);
        int nf = (s + n) * FF + f;
        out[((size_t)b * NN + s + n) * FF + f] = fmaf(y, g_scale[nf], g_shift[nf]);
    }
}

// ---------------------------------------------------------------------------
extern "C" void kernel_launch(void* const* d_in, const int* in_sizes, int n_in,
                              void* d_out, int out_size) {
    const float* input = (const float*)d_in[0];   // [8192,40,256]
    const float* adj   = (const float*)d_in[1];   // [8192,40,40]
    const float* W     = (const float*)d_in[2];   // [256,256]
    const float* gamma = (const float*)d_in[3];   // [4,10240]
    const float* beta  = (const float*)d_in[4];   // [4,10240]
    float* out = (float*)d_out;                   // [8192,40,256]

    k_gemm<<<dim3((BB * NN) / 128, FF / 128), 256>>>(input, W);
    k_stats<<<dim3(NBLK, NSPLIT), 256>>>(adj);
    k_finalize<<<(NF + 255) / 256, 256>>>(gamma, beta);
    k_norm<<<dim3(BB, NBLK), 256>>>(adj, out);
}

// round 9
// speedup vs baseline: 1.0564x; 1.0564x over previous
#include <cuda_runtime.h>
#include <cstdint>

#define BB    8192
#define NN    40
#define FF    256
#define NBLK  4
#define BLKSZ 10
#define NF    (NN * FF)          // 10240
#define EPSF  1e-5f
#define NSPLIT 128               // batch splits for stats reduction

// Scratch (static __device__ allocations, allowed by harness rules)
__device__ float g_S[(size_t)BB * NN * FF];          // 335 MB: S = X @ W
__device__ float g_psum[NSPLIT * NF];                // 5.2 MB: partial sums of Y
__device__ float g_psumsq[NSPLIT * NF];              // 5.2 MB: partial sum-squares
__device__ float g_scale[NF];
__device__ float g_shift[NF];

__device__ __forceinline__ uint32_t f2tf32(float f) {
    uint32_t r;
    asm("cvt.rna.tf32.f32 %0, %1;" : "=r"(r) : "f"(f));
    return r;
}

// ---------------------------------------------------------------------------
// K1: S = X @ W   [327680 x 256] @ [256 x 256], reading input directly.
// tf32 mma.sync.m16n8k8, fp32 accumulate. CTA tile 128x128, K-step 32,
// 256 threads = 8 warps in 4(M) x 2(N); warp tile 32x64.
// Register-prefetch pipeline: LDG next tile -> compute current -> STS next.
// ---------------------------------------------------------------------------
#define AS_STRIDE 36    // (36g mod 32 = 4g) + t covers all 32 banks -> conflict-free
#define BS_STRIDE 136   // (136t mod 32 = 8t) + g covers all 32 banks -> conflict-free

__global__ void __launch_bounds__(256) k_gemm(const float* __restrict__ X,
                                              const float* __restrict__ Bw) {
    __shared__ uint32_t As[128 * AS_STRIDE];   // [m][k], tf32 bits
    __shared__ uint32_t Bs[32 * BS_STRIDE];    // [k][n], tf32 bits

    const int tid  = threadIdx.x;
    const int lane = tid & 31;
    const int wid  = tid >> 5;
    const int wm   = wid & 3;        // 0..3  -> M offset wm*32
    const int wn   = wid >> 2;       // 0..1  -> N offset wn*64
    const int g    = lane >> 2;      // groupID
    const int t    = lane & 3;       // threadID_in_group

    const size_t m0 = (size_t)blockIdx.x * 128;
    const int    n0 = blockIdx.y * 128;

    // global->smem load mappings (K-step 32)
    const int am = tid >> 1;               // 0..127 (A row)
    const int ak = (tid & 1) * 16;         // 0 or 16 (A k-chunk of 16)
    const int bk = tid >> 3;               // 0..31  (B k row)
    const int bn = (tid & 7) * 16;         // 0..112 (B n-chunk of 16)

    const float* srcA = X + (m0 + am) * 256 + ak;   // + kk each iter

    float c[2][8][4];
#pragma unroll
    for (int i = 0; i < 2; i++)
#pragma unroll
        for (int j = 0; j < 8; j++)
#pragma unroll
            for (int q = 0; q < 4; q++) c[i][j][q] = 0.f;

    // ---- prefetch tile kk=0 into registers ----
    float4 pa[4], pb[4];
#pragma unroll
    for (int q = 0; q < 4; q++) {
        pa[q] = *(const float4*)(srcA + q * 4);
        pb[q] = *(const float4*)(Bw + (size_t)bk * 256 + n0 + bn + q * 4);
    }

    for (int kk = 0; kk < 256; kk += 32) {
        // ---- store prefetched tile to smem (cvt to tf32) ----
        {
            uint32_t* dA = &As[am * AS_STRIDE + ak];
            uint32_t* dB = &Bs[bk * BS_STRIDE + bn];
#pragma unroll
            for (int q = 0; q < 4; q++) {
                dA[q * 4 + 0] = f2tf32(pa[q].x); dA[q * 4 + 1] = f2tf32(pa[q].y);
                dA[q * 4 + 2] = f2tf32(pa[q].z); dA[q * 4 + 3] = f2tf32(pa[q].w);
                dB[q * 4 + 0] = f2tf32(pb[q].x); dB[q * 4 + 1] = f2tf32(pb[q].y);
                dB[q * 4 + 2] = f2tf32(pb[q].z); dB[q * 4 + 3] = f2tf32(pb[q].w);
            }
        }
        __syncthreads();

        // ---- issue next tile's global loads (overlap with MMA below) ----
        if (kk + 32 < 256) {
#pragma unroll
            for (int q = 0; q < 4; q++) {
                pa[q] = *(const float4*)(srcA + kk + 32 + q * 4);
                pb[q] = *(const float4*)(Bw + (size_t)(kk + 32 + bk) * 256 + n0 + bn + q * 4);
            }
        }

        // ---- compute on current smem tile ----
#pragma unroll
        for (int k0 = 0; k0 < 32; k0 += 8) {
            uint32_t a[2][4];
#pragma unroll
            for (int im = 0; im < 2; im++) {
                int rb = wm * 32 + im * 16;
                a[im][0] = As[(rb + g)     * AS_STRIDE + k0 + t];
                a[im][1] = As[(rb + g + 8) * AS_STRIDE + k0 + t];
                a[im][2] = As[(rb + g)     * AS_STRIDE + k0 + t + 4];
                a[im][3] = As[(rb + g + 8) * AS_STRIDE + k0 + t + 4];
            }
            uint32_t b[8][2];
#pragma unroll
            for (int in = 0; in < 8; in++) {
                int cb = wn * 64 + in * 8;
                b[in][0] = Bs[(k0 + t)     * BS_STRIDE + cb + g];
                b[in][1] = Bs[(k0 + t + 4) * BS_STRIDE + cb + g];
            }
#pragma unroll
            for (int im = 0; im < 2; im++)
#pragma unroll
                for (int in = 0; in < 8; in++) {
                    asm volatile(
                        "mma.sync.aligned.m16n8k8.row.col.f32.tf32.tf32.f32 "
                        "{%0,%1,%2,%3}, {%4,%5,%6,%7}, {%8,%9}, {%0,%1,%2,%3};"
                        : "+f"(c[im][in][0]), "+f"(c[im][in][1]),
                          "+f"(c[im][in][2]), "+f"(c[im][in][3])
                        : "r"(a[im][0]), "r"(a[im][1]), "r"(a[im][2]), "r"(a[im][3]),
                          "r"(b[in][0]), "r"(b[in][1]));
                }
        }
        __syncthreads();
    }

    // ---- epilogue: write S ----
#pragma unroll
    for (int im = 0; im < 2; im++) {
        size_t r0 = m0 + wm * 32 + im * 16 + g;
#pragma unroll
        for (int in = 0; in < 8; in++) {
            int col = n0 + wn * 64 + in * 8 + 2 * t;
            *(float2*)(g_S + r0 * 256 + col)       = make_float2(c[im][in][0], c[im][in][1]);
            *(float2*)(g_S + (r0 + 8) * 256 + col) = make_float2(c[im][in][2], c[im][in][3]);
        }
    }
}

// ---------------------------------------------------------------------------
// K2: stats with on-the-fly block-mix. Y[b,s+n,f] = sum_j adj[b,s+n,s+j]*S[b,s+j,f]
// grid (NBLK, NSPLIT), 256 threads (one per f). Deterministic, no atomics.
// ---------------------------------------------------------------------------
__global__ void __launch_bounds__(256) k_stats(const float* __restrict__ adj) {
    __shared__ float a_s[BLKSZ][BLKSZ];
    const int blk = blockIdx.x;
    const int sp  = blockIdx.y;
    const int s   = blk * BLKSZ;
    const int f   = threadIdx.x;
    const int b0  = sp * (BB / NSPLIT);

    float sum[BLKSZ], sq[BLKSZ];
#pragma unroll
    for (int n = 0; n < BLKSZ; n++) { sum[n] = 0.f; sq[n] = 0.f; }

    for (int b = b0; b < b0 + BB / NSPLIT; b++) {
        if (f < BLKSZ * BLKSZ) {
            int n = f / BLKSZ, j = f % BLKSZ;
            a_s[n][j] = adj[((size_t)b * NN + s + n) * NN + s + j];
        }
        __syncthreads();

        float x[BLKSZ];
#pragma unroll
        for (int j = 0; j < BLKSZ; j++)
            x[j] = g_S[((size_t)b * NN + s + j) * FF + f];

#pragma unroll
        for (int n = 0; n < BLKSZ; n++) {
            float y = 0.f;
#pragma unroll
            for (int j = 0; j < BLKSZ; j++)
                y = fmaf(a_s[n][j], x[j], y);
            sum[n] += y;
            sq[n]   = fmaf(y, y, sq[n]);
        }
        __syncthreads();
    }

#pragma unroll
    for (int n = 0; n < BLKSZ; n++) {
        g_psum[sp * NF + (s + n) * FF + f]   = sum[n];
        g_psumsq[sp * NF + (s + n) * FF + f] = sq[n];
    }
}

// ---------------------------------------------------------------------------
// K3: reduce partials, compute per-feature scale/shift.
// out = (Y - mean) * rsqrt(var+eps) * gamma[blk(n)]  +  sum_i beta[i]
// (rows outside block i contribute exactly beta[i] from that block's BN)
// ---------------------------------------------------------------------------
__global__ void k_finalize(const float* __restrict__ gamma,
                           const float* __restrict__ beta) {
    int i = blockIdx.x * blockDim.x + threadIdx.x;
    if (i >= NF) return;
    float s = 0.f, s2 = 0.f;
#pragma unroll 8
    for (int sp = 0; sp < NSPLIT; sp++) {
        s  += g_psum[sp * NF + i];
        s2 += g_psumsq[sp * NF + i];
    }
    const float inv = 1.f / (float)BB;
    float mean = s * inv;
    float var  = s2 * inv - mean * mean;
    int n   = i / FF;
    int blk = n / BLKSZ;
    float sc = rsqrtf(var + EPSF) * gamma[blk * NF + i];
    float sh = -mean * sc;
#pragma unroll
    for (int t = 0; t < NBLK; t++) sh += beta[t * NF + i];
    g_scale[i] = sc;
    g_shift[i] = sh;
}

// ---------------------------------------------------------------------------
// K4: recompute Y = mix(S), apply scale/shift, write out.
// grid (BB, NBLK), 256 threads (one per f)
// ---------------------------------------------------------------------------
__global__ void __launch_bounds__(256) k_norm(const float* __restrict__ adj,
                                              float* __restrict__ out) {
    __shared__ float a_s[BLKSZ][BLKSZ];
    const int b   = blockIdx.x;
    const int blk = blockIdx.y;
    const int s   = blk * BLKSZ;
    const int f   = threadIdx.x;

    if (f < BLKSZ * BLKSZ) {
        int n = f / BLKSZ, j = f % BLKSZ;
        a_s[n][j] = adj[((size_t)b * NN + s + n) * NN + s + j];
    }
    __syncthreads();

    float x[BLKSZ];
#pragma unroll
    for (int j = 0; j < BLKSZ; j++)
        x[j] = g_S[((size_t)b * NN + s + j) * FF + f];

#pragma unroll
    for (int n = 0; n < BLKSZ; n++) {
        float y = 0.f;
#pragma unroll
        for (int j = 0; j < BLKSZ; j++)
            y = fmaf(a_s[n][j], x[j], y);
        int nf = (s + n) * FF + f;
        out[((size_t)b * NN + s + n) * FF + f] = fmaf(y, g_scale[nf], g_shift[nf]);
    }
}

// ---------------------------------------------------------------------------
extern "C" void kernel_launch(void* const* d_in, const int* in_sizes, int n_in,
                              void* d_out, int out_size) {
    const float* input = (const float*)d_in[0];   // [8192,40,256]
    const float* adj   = (const float*)d_in[1];   // [8192,40,40]
    const float* W     = (const float*)d_in[2];   // [256,256]
    const float* gamma = (const float*)d_in[3];   // [4,10240]
    const float* beta  = (const float*)d_in[4];   // [4,10240]
    float* out = (float*)d_out;                   // [8192,40,256]

    k_gemm<<<dim3((BB * NN) / 128, FF / 128), 256>>>(input, W);
    k_stats<<<dim3(NBLK, NSPLIT), 256>>>(adj);
    k_finalize<<<(NF + 255) / 256, 256>>>(gamma, beta);
    k_norm<<<dim3(BB, NBLK), 256>>>(adj, out);
}